// round 13
// baseline (speedup 1.0000x reference)
#include <cuda_runtime.h>
#include <cuda_bf16.h>
#include <cuda_fp16.h>
#include <cstdint>
#include <cstddef>

// ---------------- problem constants ----------------
#define NHEAD 8
#define HD 32
#define NTOK 256
#define BATCH 256
#define DIMC 256
#define NGROUP 64
#define PD 16
#define LREL 961
#define QSCALE 0.17677669529663687f
#define MROWS (BATCH * NTOK)          // 65536

// ---------------- device scratch ----------------
__device__ float g_qh[(size_t)MROWS * DIMC];           // scaled Q (fp32)
__device__ float g_kv[(size_t)MROWS * 2 * DIMC];       // K|V (fp32)
__device__ float g_pos[LREL * NHEAD];
__device__ __half g_rpbh[NHEAD * NTOK * NTOK];
__device__ __half g_maskh[NGROUP * NTOK * NTOK];
// packed weights [row][pair]
__device__ uint32_t g_qwhi[256 * 128],  g_qwlo[256 * 128];
__device__ uint32_t g_kvwhi[512 * 128], g_kvwlo[512 * 128];
__device__ uint32_t g_pwhi[256 * 128],  g_pwlo[256 * 128];
__device__ float g_qbs[256];
// pre-converted activations (bf16 hi/lo pairs) [row][pair]
__device__ uint32_t g_qihi[(size_t)MROWS * 128], g_qilo[(size_t)MROWS * 128];
__device__ uint32_t g_kihi[(size_t)MROWS * 128], g_kilo[(size_t)MROWS * 128];
// attention output packed [row][pair]
__device__ uint32_t g_xhi[(size_t)MROWS * 128], g_xlo[(size_t)MROWS * 128];

// ---------------- helpers ----------------
__device__ __forceinline__ uint32_t smem_u32(const void* p) {
    uint32_t a;
    asm("{ .reg .u64 t; cvta.to.shared.u64 t, %1; cvt.u32.u64 %0, t; }" : "=r"(a) : "l"(p));
    return a;
}
__device__ __forceinline__ void cp16(uint32_t saddr, const void* g) {
    asm volatile("cp.async.cg.shared.global [%0], [%1], 16;" :: "r"(saddr), "l"(g) : "memory");
}
__device__ __forceinline__ void cp_commit() { asm volatile("cp.async.commit_group;" ::: "memory"); }
__device__ __forceinline__ void cp_wait0() { asm volatile("cp.async.wait_group 0;" ::: "memory"); }
__device__ __forceinline__ void cp_wait1() { asm volatile("cp.async.wait_group 1;" ::: "memory"); }

__device__ __forceinline__ void pack_bf16_pair(float x, float y, uint32_t& hi, uint32_t& lo) {
    __nv_bfloat16 hx = __float2bfloat16_rn(x);
    __nv_bfloat16 hy = __float2bfloat16_rn(y);
    float rx = x - __bfloat162float(hx);
    float ry = y - __bfloat162float(hy);
    __nv_bfloat16 lx = __float2bfloat16_rn(rx);
    __nv_bfloat16 ly = __float2bfloat16_rn(ry);
    hi = ((uint32_t)__bfloat16_as_ushort(hy) << 16) | (uint32_t)__bfloat16_as_ushort(hx);
    lo = ((uint32_t)__bfloat16_as_ushort(ly) << 16) | (uint32_t)__bfloat16_as_ushort(lx);
}
__device__ __forceinline__ void mma_bf16(float* d, const uint32_t* a, const uint32_t* b) {
    asm volatile("mma.sync.aligned.m16n8k16.row.col.f32.bf16.bf16.f32 "
        "{%0,%1,%2,%3}, {%4,%5,%6,%7}, {%8,%9}, {%0,%1,%2,%3};"
        : "+f"(d[0]), "+f"(d[1]), "+f"(d[2]), "+f"(d[3])
        : "r"(a[0]), "r"(a[1]), "r"(a[2]), "r"(a[3]), "r"(b[0]), "r"(b[1]));
}
__device__ __forceinline__ void mma_f16(float* d, const uint32_t* a, const uint32_t* b) {
    asm volatile("mma.sync.aligned.m16n8k16.row.col.f32.f16.f16.f32 "
        "{%0,%1,%2,%3}, {%4,%5,%6,%7}, {%8,%9}, {%0,%1,%2,%3};"
        : "+f"(d[0]), "+f"(d[1]), "+f"(d[2]), "+f"(d[3])
        : "r"(a[0]), "r"(a[1]), "r"(a[2]), "r"(a[3]), "r"(b[0]), "r"(b[1]));
}

// ---------------- pre-conversion kernels ----------------
__global__ void conv_w_kernel(const float* __restrict__ qw, const float* __restrict__ kvw,
                              const float* __restrict__ pw, const float* __restrict__ qb) {
    int idx = blockIdx.x * 256 + threadIdx.x;
    int row = idx >> 7, p = idx & 127;
    const float* src;
    uint32_t *dh, *dl;
    float sc = 1.f;
    if (row < 256)      { src = qw + row * 256;          dh = g_qwhi + row * 128 + p;          dl = g_qwlo + row * 128 + p;          sc = QSCALE; }
    else if (row < 768) { int r = row - 256; src = kvw + r * 256; dh = g_kvwhi + r * 128 + p;  dl = g_kvwlo + r * 128 + p; }
    else                { int r = row - 768; src = pw + r * 256;  dh = g_pwhi + r * 128 + p;   dl = g_pwlo + r * 128 + p; }
    uint32_t hi, lo;
    pack_bf16_pair(src[2 * p] * sc, src[2 * p + 1] * sc, hi, lo);
    *dh = hi; *dl = lo;
    if (idx < 256) g_qbs[idx] = qb[idx] * QSCALE;
}

// pre-convert q/k inputs to packed bf16 hi/lo pairs
__global__ void conv_in_kernel(const float* __restrict__ q, const float* __restrict__ kf) {
    size_t idx = (size_t)blockIdx.x * 256 + threadIdx.x;   // 0 .. 2*MROWS*128-1
    const size_t half = (size_t)MROWS * 128;
    bool isK = idx >= half;
    size_t li = isK ? idx - half : idx;
    const float* src = isK ? kf : q;
    float2 v = *(const float2*)(src + li * 2);
    uint32_t hi, lo;
    pack_bf16_pair(v.x, v.y, hi, lo);
    if (isK) { g_kihi[li] = hi; g_kilo[li] = lo; }
    else     { g_qihi[li] = hi; g_qilo[li] = lo; }
}

__global__ void conv_mask_kernel(const float* __restrict__ mask) {
    int i = blockIdx.x * 256 + threadIdx.x;    // pairs: NGROUP*256*256/2
    float2 v = *(const float2*)(mask + (size_t)i * 2);
    __half2 h2 = __floats2half2_rn(v.x, v.y);
    *(__half2*)(g_maskh + (size_t)i * 2) = h2;
}

// ---------------- pos-bias MLP ----------------
__device__ __forceinline__ void ln16(float* x, const float* g, const float* b) {
    float m = 0.f;
#pragma unroll
    for (int i = 0; i < PD; i++) m += x[i];
    m *= (1.0f / PD);
    float v = 0.f;
#pragma unroll
    for (int i = 0; i < PD; i++) { float d = x[i] - m; v += d * d; }
    v *= (1.0f / PD);
    float inv = rsqrtf(v + 1e-5f);
#pragma unroll
    for (int i = 0; i < PD; i++) x[i] = (x[i] - m) * inv * g[i] + b[i];
}

__global__ void pos_mlp_kernel(const float* __restrict__ pp_w, const float* __restrict__ pp_b,
                               const float* __restrict__ ln1_g, const float* __restrict__ ln1_b,
                               const float* __restrict__ l1_w,  const float* __restrict__ l1_b,
                               const float* __restrict__ ln2_g, const float* __restrict__ ln2_b,
                               const float* __restrict__ l2_w,  const float* __restrict__ l2_b,
                               const float* __restrict__ ln3_g, const float* __restrict__ ln3_b,
                               const float* __restrict__ l3_w,  const float* __restrict__ l3_b) {
    int p = blockIdx.x * blockDim.x + threadIdx.x;
    if (p >= LREL) return;
    float b0 = (float)(p / 31 - 15);
    float b1 = (float)(p % 31 - 15);
    float x[PD], y[PD];
#pragma unroll
    for (int o = 0; o < PD; o++) x[o] = b0 * pp_w[o * 2 + 0] + b1 * pp_w[o * 2 + 1] + pp_b[o];
    ln16(x, ln1_g, ln1_b);
#pragma unroll
    for (int o = 0; o < PD; o++) {
        float s = l1_b[o];
#pragma unroll
        for (int i = 0; i < PD; i++) s += fmaxf(x[i], 0.f) * l1_w[o * PD + i];
        y[o] = s;
    }
#pragma unroll
    for (int o = 0; o < PD; o++) x[o] = y[o];
    ln16(x, ln2_g, ln2_b);
#pragma unroll
    for (int o = 0; o < PD; o++) {
        float s = l2_b[o];
#pragma unroll
        for (int i = 0; i < PD; i++) s += fmaxf(x[i], 0.f) * l2_w[o * PD + i];
        y[o] = s;
    }
#pragma unroll
    for (int o = 0; o < PD; o++) x[o] = y[o];
    ln16(x, ln3_g, ln3_b);
#pragma unroll
    for (int h = 0; h < NHEAD; h++) {
        float s = l3_b[h];
#pragma unroll
        for (int i = 0; i < PD; i++) s += fmaxf(x[i], 0.f) * l3_w[h * PD + i];
        g_pos[p * NHEAD + h] = s;
    }
}

__global__ void rpb_fill_kernel() {
    int i = blockIdx.x * 256 + threadIdx.x;
    int h = i >> 16;
    int rem = i & 65535;
    int n = rem >> 8;
    int m = rem & 255;
    int di = (n >> 4) - (m >> 4) + 15;
    int dj = (n & 15) - (m & 15) + 15;
    g_rpbh[i] = __float2half(g_pos[(di * 31 + dj) * NHEAD + h]);
}

// ---------------- GEMM infrastructure ----------------
#define SWZ(r, c) (((r) << 4) + ((c) ^ ((((r) >> 1) & 3) << 2)))
#define GSW_TILE 2048
#define GSW_STAGE 8192

__device__ __forceinline__ void fill_packed_async(uint32_t sbase, int st, int baseoff, int tid,
                                                  const uint32_t* Whi, const uint32_t* Wlo,
                                                  int r0, int kc) {
#pragma unroll
    for (int i = 0; i < 2; i++) {
        int idx = tid * 2 + i;
        int row = idx >> 2, c4 = (idx & 3) << 2;
        uint32_t off = (uint32_t)((st * GSW_STAGE + baseoff + SWZ(row, c4)) * 4);
        size_t gidx = (size_t)(r0 + row) * 128 + kc * 16 + c4;
        cp16(sbase + off, Whi + gidx);
        cp16(sbase + off + GSW_TILE * 4, Wlo + gidx);
    }
}

// round-9 scalar-LDS compute (best measured)
__device__ __forceinline__ void gemm_compute(uint32_t* st, int wm, int wn, int g, int tg,
                                             float acc[4][4][4]) {
    uint32_t* sAhi = st;                uint32_t* sAlo = st + GSW_TILE;
    uint32_t* sBhi = st + 2 * GSW_TILE; uint32_t* sBlo = st + 3 * GSW_TILE;
#pragma unroll
    for (int ks = 0; ks < 2; ks++) {
        int pc = ks * 8 + tg;
        uint32_t ahi[4][4], alo[4][4], bhi[4][2], blo[4][2];
#pragma unroll
        for (int mt = 0; mt < 4; mt++) {
            int ra = wm + mt * 16 + g;
            ahi[mt][0] = sAhi[SWZ(ra, pc)];         alo[mt][0] = sAlo[SWZ(ra, pc)];
            ahi[mt][1] = sAhi[SWZ(ra + 8, pc)];     alo[mt][1] = sAlo[SWZ(ra + 8, pc)];
            ahi[mt][2] = sAhi[SWZ(ra, pc + 4)];     alo[mt][2] = sAlo[SWZ(ra, pc + 4)];
            ahi[mt][3] = sAhi[SWZ(ra + 8, pc + 4)]; alo[mt][3] = sAlo[SWZ(ra + 8, pc + 4)];
        }
#pragma unroll
        for (int nt = 0; nt < 4; nt++) {
            int rb = wn + nt * 8 + g;
            bhi[nt][0] = sBhi[SWZ(rb, pc)]; bhi[nt][1] = sBhi[SWZ(rb, pc + 4)];
            blo[nt][0] = sBlo[SWZ(rb, pc)]; blo[nt][1] = sBlo[SWZ(rb, pc + 4)];
        }
#pragma unroll
        for (int mt = 0; mt < 4; mt++)
#pragma unroll
            for (int nt = 0; nt < 4; nt++) {
                mma_bf16(acc[mt][nt], ahi[mt], bhi[nt]);
                mma_bf16(acc[mt][nt], ahi[mt], blo[nt]);
                mma_bf16(acc[mt][nt], alo[mt], bhi[nt]);
            }
    }
}

// ---------------- merged Q + KV projection GEMM (fully async A and B) ----------------
__global__ __launch_bounds__(256, 2)
void gemm_qkv(const float* __restrict__ kv_b) {
    extern __shared__ uint32_t gsm[];
    uint32_t sbase = smem_u32(gsm);
    int tid = threadIdx.x, lane = tid & 31, wid = tid >> 5;
    int bx = blockIdx.x, m0 = blockIdx.y * 128;
    const uint32_t *Ahi, *Alo, *Whi, *Wlo; float* C; const float* bias; int Ncols, n0;
    if (bx < 2) { Ahi = g_qihi; Alo = g_qilo; Whi = g_qwhi;  Wlo = g_qwlo;  C = g_qh; bias = g_qbs; Ncols = 256; n0 = bx * 128; }
    else        { Ahi = g_kihi; Alo = g_kilo; Whi = g_kvwhi; Wlo = g_kvwlo; C = g_kv; bias = kv_b;  Ncols = 512; n0 = (bx - 2) * 128; }

    int wm = (wid >> 2) * 64, wn = (wid & 3) * 32;
    int g = lane >> 2, tg = lane & 3;

    float acc[4][4][4];
#pragma unroll
    for (int a = 0; a < 4; a++)
#pragma unroll
        for (int bq = 0; bq < 4; bq++)
#pragma unroll
            for (int c = 0; c < 4; c++) acc[a][bq][c] = 0.f;

    fill_packed_async(sbase, 0, 0, tid, Ahi, Alo, m0, 0);
    fill_packed_async(sbase, 0, 2 * GSW_TILE, tid, Whi, Wlo, n0, 0);
    cp_commit();

    for (int kc = 0; kc < 8; kc++) {
        int s = kc & 1;
        bool pre = (kc + 1 < 8);
        if (pre) {
            fill_packed_async(sbase, s ^ 1, 0, tid, Ahi, Alo, m0, kc + 1);
            fill_packed_async(sbase, s ^ 1, 2 * GSW_TILE, tid, Whi, Wlo, n0, kc + 1);
            cp_commit();
            cp_wait1();
        } else {
            cp_wait0();
        }
        __syncthreads();
        gemm_compute(gsm + s * GSW_STAGE, wm, wn, g, tg, acc);
        __syncthreads();
    }

#pragma unroll
    for (int mt = 0; mt < 4; mt++) {
        int r0 = m0 + wm + mt * 16 + g;
#pragma unroll
        for (int nt = 0; nt < 4; nt++) {
            int col = n0 + wn + nt * 8 + 2 * tg;
            float bb0 = bias[col], bb1 = bias[col + 1];
            float2 v0, v1;
            v0.x = acc[mt][nt][0] + bb0; v0.y = acc[mt][nt][1] + bb1;
            v1.x = acc[mt][nt][2] + bb0; v1.y = acc[mt][nt][3] + bb1;
            *(float2*)(C + (size_t)r0 * Ncols + col) = v0;
            *(float2*)(C + (size_t)(r0 + 8) * Ncols + col) = v1;
        }
    }
}

// ---------------- output projection GEMM ----------------
__global__ __launch_bounds__(256, 2)
void gemm_proj(const float* __restrict__ proj_b, float* __restrict__ out) {
    extern __shared__ uint32_t gsm[];
    uint32_t sbase = smem_u32(gsm);
    int tid = threadIdx.x, lane = tid & 31, wid = tid >> 5;
    int m0 = blockIdx.y * 128, n0 = blockIdx.x * 128;
    int wm = (wid >> 2) * 64, wn = (wid & 3) * 32;
    int g = lane >> 2, tg = lane & 3;

    float acc[4][4][4];
#pragma unroll
    for (int a = 0; a < 4; a++)
#pragma unroll
        for (int bq = 0; bq < 4; bq++)
#pragma unroll
            for (int c = 0; c < 4; c++) acc[a][bq][c] = 0.f;

    fill_packed_async(sbase, 0, 0, tid, g_xhi, g_xlo, m0, 0);
    fill_packed_async(sbase, 0, 2 * GSW_TILE, tid, g_pwhi, g_pwlo, n0, 0);
    cp_commit();

    for (int kc = 0; kc < 8; kc++) {
        int s = kc & 1;
        bool pre = (kc + 1 < 8);
        if (pre) {
            fill_packed_async(sbase, s ^ 1, 0, tid, g_xhi, g_xlo, m0, kc + 1);
            fill_packed_async(sbase, s ^ 1, 2 * GSW_TILE, tid, g_pwhi, g_pwlo, n0, kc + 1);
            cp_commit();
            cp_wait1();
        } else {
            cp_wait0();
        }
        __syncthreads();
        gemm_compute(gsm + s * GSW_STAGE, wm, wn, g, tg, acc);
        __syncthreads();
    }

#pragma unroll
    for (int mt = 0; mt < 4; mt++) {
        int r0 = m0 + wm + mt * 16 + g;
#pragma unroll
        for (int nt = 0; nt < 4; nt++) {
            int col = n0 + wn + nt * 8 + 2 * tg;
            float bb0 = proj_b[col], bb1 = proj_b[col + 1];
            float2 v0, v1;
            v0.x = acc[mt][nt][0] + bb0; v0.y = acc[mt][nt][1] + bb1;
            v1.x = acc[mt][nt][2] + bb0; v1.y = acc[mt][nt][3] + bb1;
            *(float2*)(out + (size_t)r0 * 256 + col) = v0;
            *(float2*)(out + (size_t)(r0 + 8) * 256 + col) = v1;
        }
    }
}

// ---------------- fused attention (round-9 form, f16 rpb/mask) ----------------
#define KSTR 20
#define VSTR 133
#define A_KHI 0
#define A_KLO 5120
#define A_QHI 10240
#define A_QLO 12800
#define A_VT  15360
#define A_TOT 19616
__global__ __launch_bounds__(256, 1)
void attn_kernel() {
    extern __shared__ uint32_t smu[];
    uint32_t* Khi = smu + A_KHI;
    uint32_t* Klo = smu + A_KLO;
    uint32_t* Qhi = smu + A_QHI;
    uint32_t* Qlo = smu + A_QLO;
    uint32_t* Vt  = smu + A_VT;
    __half*  Vth = (__half*)Vt;

    int tid = threadIdx.x, lane = tid & 31, w = tid >> 5;
    int r0 = blockIdx.x * 128, h = blockIdx.y, b = blockIdx.z;
    int g = lane >> 2, tg = lane & 3;

    {
        int key8 = tid >> 3, d4 = (tid & 7) * 4;
#pragma unroll
        for (int it = 0; it < 8; it++) {
            int key = it * 32 + key8;
            const float* src = g_kv + (size_t)(b * NTOK + key) * (2 * DIMC) + h * HD + d4;
            float4 kx = *(const float4*)src;
            float4 vx = *(const float4*)(src + DIMC);
            uint32_t h0, l0, h1, l1;
            pack_bf16_pair(kx.x, kx.y, h0, l0);
            pack_bf16_pair(kx.z, kx.w, h1, l1);
            int kb = key * KSTR + (d4 >> 1);
            Khi[kb] = h0; Khi[kb + 1] = h1;
            Klo[kb] = l0; Klo[kb + 1] = l1;
            Vth[(d4 + 0) * (2 * VSTR) + key] = __float2half_rn(vx.x);
            Vth[(d4 + 1) * (2 * VSTR) + key] = __float2half_rn(vx.y);
            Vth[(d4 + 2) * (2 * VSTR) + key] = __float2half_rn(vx.z);
            Vth[(d4 + 3) * (2 * VSTR) + key] = __float2half_rn(vx.w);
        }
#pragma unroll
        for (int it = 0; it < 4; it++) {
            int row = it * 32 + key8;
            float4 qx = *(const float4*)(g_qh + (size_t)(b * NTOK + r0 + row) * DIMC + h * HD + d4);
            uint32_t h0, l0, h1, l1;
            pack_bf16_pair(qx.x, qx.y, h0, l0);
            pack_bf16_pair(qx.z, qx.w, h1, l1);
            int qb = row * KSTR + (d4 >> 1);
            Qhi[qb] = h0; Qhi[qb + 1] = h1;
            Qlo[qb] = l0; Qlo[qb + 1] = l1;
        }
    }
    __syncthreads();

    int wm = w * 16;

    uint32_t qh_[2][4], ql_[2][4];
#pragma unroll
    for (int ks = 0; ks < 2; ks++) {
        int ra = (wm + g) * KSTR + ks * 8 + tg;
        int rb = (wm + 8 + g) * KSTR + ks * 8 + tg;
        qh_[ks][0] = Qhi[ra]; qh_[ks][1] = Qhi[rb];
        qh_[ks][2] = Qhi[ra + 4]; qh_[ks][3] = Qhi[rb + 4];
        ql_[ks][0] = Qlo[ra]; ql_[ks][1] = Qlo[rb];
        ql_[ks][2] = Qlo[ra + 4]; ql_[ks][3] = Qlo[rb + 4];
    }

    float sc[32][4];
#pragma unroll
    for (int j = 0; j < 32; j++) { sc[j][0] = 0.f; sc[j][1] = 0.f; sc[j][2] = 0.f; sc[j][3] = 0.f; }
#pragma unroll
    for (int j = 0; j < 32; j++) {
#pragma unroll
        for (int ks = 0; ks < 2; ks++) {
            int kb = (j * 8 + g) * KSTR + ks * 8 + tg;
            uint32_t bh[2], bl[2];
            bh[0] = Khi[kb]; bh[1] = Khi[kb + 4];
            bl[0] = Klo[kb]; bl[1] = Klo[kb + 4];
            mma_bf16(sc[j], qh_[ks], bh);
            mma_bf16(sc[j], qh_[ks], bl);
            mma_bf16(sc[j], ql_[ks], bh);
        }
    }

    int R0 = r0 + wm + g;
    const __half* rpbR = g_rpbh + ((size_t)h * NTOK + R0) * NTOK;
    const __half* mkR  = g_maskh + ((size_t)(b & (NGROUP - 1)) * NTOK + R0) * NTOK;
#pragma unroll
    for (int j = 0; j < 32; j++) {
        int c = j * 8 + 2 * tg;
        float2 r0v = __half22float2(*(const __half2*)(rpbR + c));
        float2 r1v = __half22float2(*(const __half2*)(rpbR + 8 * NTOK + c));
        float2 m0v = __half22float2(*(const __half2*)(mkR + c));
        float2 m1v = __half22float2(*(const __half2*)(mkR + 8 * NTOK + c));
        sc[j][0] += r0v.x + m0v.x; sc[j][1] += r0v.y + m0v.y;
        sc[j][2] += r1v.x + m1v.x; sc[j][3] += r1v.y + m1v.y;
    }

    float mx0 = -1e30f, mx1 = -1e30f;
#pragma unroll
    for (int j = 0; j < 32; j++) {
        mx0 = fmaxf(mx0, fmaxf(sc[j][0], sc[j][1]));
        mx1 = fmaxf(mx1, fmaxf(sc[j][2], sc[j][3]));
    }
    mx0 = fmaxf(mx0, __shfl_xor_sync(0xffffffffu, mx0, 1));
    mx0 = fmaxf(mx0, __shfl_xor_sync(0xffffffffu, mx0, 2));
    mx1 = fmaxf(mx1, __shfl_xor_sync(0xffffffffu, mx1, 1));
    mx1 = fmaxf(mx1, __shfl_xor_sync(0xffffffffu, mx1, 2));

    uint32_t pf[16][4];
    float sum0 = 0.f, sum1 = 0.f;
#pragma unroll
    for (int jj = 0; jj < 16; jj++) {
        __half2 e0 = h2exp(__floats2half2_rn(sc[2 * jj][0] - mx0, sc[2 * jj][1] - mx0));
        __half2 e1 = h2exp(__floats2half2_rn(sc[2 * jj][2] - mx1, sc[2 * jj][3] - mx1));
        __half2 e2 = h2exp(__floats2half2_rn(sc[2 * jj + 1][0] - mx0, sc[2 * jj + 1][1] - mx0));
        __half2 e3 = h2exp(__floats2half2_rn(sc[2 * jj + 1][2] - mx1, sc[2 * jj + 1][3] - mx1));
        pf[jj][0] = *(uint32_t*)&e0;
        pf[jj][1] = *(uint32_t*)&e1;
        pf[jj][2] = *(uint32_t*)&e2;
        pf[jj][3] = *(uint32_t*)&e3;
        float2 f0 = __half22float2(e0), f1 = __half22float2(e1);
        float2 f2 = __half22float2(e2), f3 = __half22float2(e3);
        sum0 += f0.x + f0.y + f2.x + f2.y;
        sum1 += f1.x + f1.y + f3.x + f3.y;
    }
    sum0 += __shfl_xor_sync(0xffffffffu, sum0, 1);
    sum0 += __shfl_xor_sync(0xffffffffu, sum0, 2);
    sum1 += __shfl_xor_sync(0xffffffffu, sum1, 1);
    sum1 += __shfl_xor_sync(0xffffffffu, sum1, 2);
    float inv0 = 1.0f / sum0, inv1 = 1.0f / sum1;

    size_t ro0 = (size_t)(b * NTOK + R0) * 128;
    size_t ro1 = ro0 + 8 * 128;
#pragma unroll
    for (int dt = 0; dt < 4; dt++) {
        float ob[4] = {0.f, 0.f, 0.f, 0.f};
#pragma unroll
        for (int kt = 0; kt < 16; kt++) {
            int vb = (dt * 8 + g) * VSTR + kt * 8 + tg;
            uint32_t bv[2];
            bv[0] = Vt[vb]; bv[1] = Vt[vb + 4];
            mma_f16(ob, pf[kt], bv);
        }
        int pc = h * 16 + dt * 4 + tg;
        uint32_t hi0, lo0, hi1, lo1;
        pack_bf16_pair(ob[0] * inv0, ob[1] * inv0, hi0, lo0);
        pack_bf16_pair(ob[2] * inv1, ob[3] * inv1, hi1, lo1);
        g_xhi[ro0 + pc] = hi0; g_xlo[ro0 + pc] = lo0;
        g_xhi[ro1 + pc] = hi1; g_xlo[ro1 + pc] = lo1;
    }
}

// ---------------- launch ----------------
extern "C" void kernel_launch(void* const* d_in, const int* in_sizes, int n_in,
                              void* d_out, int out_size) {
    const float* q      = (const float*)d_in[0];
    const float* k      = (const float*)d_in[1];
    const float* mask   = (const float*)d_in[2];
    const float* q_w    = (const float*)d_in[3];
    const float* q_b    = (const float*)d_in[4];
    const float* kv_w   = (const float*)d_in[5];
    const float* kv_b   = (const float*)d_in[6];
    const float* proj_w = (const float*)d_in[7];
    const float* proj_b = (const float*)d_in[8];
    const float* pp_w   = (const float*)d_in[9];
    const float* pp_b   = (const float*)d_in[10];
    const float* ln1_g  = (const float*)d_in[11];
    const float* ln1_b  = (const float*)d_in[12];
    const float* l1_w   = (const float*)d_in[13];
    const float* l1_b   = (const float*)d_in[14];
    const float* ln2_g  = (const float*)d_in[15];
    const float* ln2_b  = (const float*)d_in[16];
    const float* l2_w   = (const float*)d_in[17];
    const float* l2_b   = (const float*)d_in[18];
    const float* ln3_g  = (const float*)d_in[19];
    const float* ln3_b  = (const float*)d_in[20];
    const float* l3_w   = (const float*)d_in[21];
    const float* l3_b   = (const float*)d_in[22];
    (void)in_sizes; (void)n_in; (void)out_size;

    int gsmem = 2 * GSW_STAGE * (int)sizeof(uint32_t);   // 65536
    int asmem = A_TOT * (int)sizeof(uint32_t);           // 78464
    static int attr_done = 0;
    if (!attr_done) {
        cudaFuncSetAttribute(gemm_qkv, cudaFuncAttributeMaxDynamicSharedMemorySize, gsmem);
        cudaFuncSetAttribute(gemm_proj, cudaFuncAttributeMaxDynamicSharedMemorySize, gsmem);
        cudaFuncSetAttribute(attn_kernel, cudaFuncAttributeMaxDynamicSharedMemorySize, asmem);
        attr_done = 1;
    }

    conv_w_kernel<<<512, 256>>>(q_w, kv_w, proj_w, q_b);
    conv_in_kernel<<<2 * MROWS * 128 / 256, 256>>>(q, k);
    pos_mlp_kernel<<<4, 256>>>(pp_w, pp_b, ln1_g, ln1_b, l1_w, l1_b,
                               ln2_g, ln2_b, l2_w, l2_b, ln3_g, ln3_b, l3_w, l3_b);
    rpb_fill_kernel<<<NHEAD * NTOK * NTOK / 256, 256>>>();
    conv_mask_kernel<<<NGROUP * NTOK * NTOK / 512, 256>>>(mask);

    gemm_qkv<<<dim3(6, 512), 256, gsmem>>>(kv_b);
    attn_kernel<<<dim3(2, NHEAD, BATCH), 256, asmem>>>();
    gemm_proj<<<dim3(2, 512), 256, gsmem>>>(proj_b, (float*)d_out);
}

// round 15
// speedup vs baseline: 1.2977x; 1.2977x over previous
#include <cuda_runtime.h>
#include <cuda_bf16.h>
#include <cuda_fp16.h>
#include <cstdint>
#include <cstddef>

// ---------------- problem constants ----------------
#define NHEAD 8
#define HD 32
#define NTOK 256
#define BATCH 256
#define DIMC 256
#define NGROUP 64
#define PD 16
#define LREL 961
#define QSCALE 0.17677669529663687f
#define MROWS (BATCH * NTOK)

// ---------------- device scratch ----------------
__device__ float g_qh[(size_t)MROWS * DIMC];          // scaled Q (fp32)
__device__ float g_kv[(size_t)MROWS * 2 * DIMC];      // K|V (fp32)
__device__ float g_pos[LREL * NHEAD];
__device__ float g_rpb[NHEAD * NTOK * NTOK];
// weights pre-split to f16 hi/lo pairs [row][pair]
__device__ uint32_t g_qwhi[256 * 128],  g_qwlo[256 * 128];
__device__ uint32_t g_kvwhi[512 * 128], g_kvwlo[512 * 128];
__device__ uint32_t g_pwhi[256 * 128],  g_pwlo[256 * 128];
__device__ float g_qbs[256];
// attention output, single f16 pairs [row][pair]
__device__ uint32_t g_xf[(size_t)MROWS * 128];

// ---------------- helpers ----------------
__device__ __forceinline__ uint32_t smem_u32(const void* p) {
    uint32_t a;
    asm("{ .reg .u64 t; cvta.to.shared.u64 t, %1; cvt.u32.u64 %0, t; }" : "=r"(a) : "l"(p));
    return a;
}
__device__ __forceinline__ void cp16(uint32_t saddr, const void* g) {
    asm volatile("cp.async.cg.shared.global [%0], [%1], 16;" :: "r"(saddr), "l"(g) : "memory");
}
__device__ __forceinline__ void cp_commit() { asm volatile("cp.async.commit_group;" ::: "memory"); }
__device__ __forceinline__ void cp_wait0() { asm volatile("cp.async.wait_group 0;" ::: "memory"); }
__device__ __forceinline__ void cp_wait1() { asm volatile("cp.async.wait_group 1;" ::: "memory"); }

__device__ __forceinline__ uint32_t packh2(float x, float y) {
    __half2 h = __floats2half2_rn(x, y);
    return *(uint32_t*)&h;
}
__device__ __forceinline__ void packh2_split(float x, float y, uint32_t& hi, uint32_t& lo) {
    __half2 h = __floats2half2_rn(x, y);
    float2 f = __half22float2(h);
    __half2 l = __floats2half2_rn(x - f.x, y - f.y);
    hi = *(uint32_t*)&h;
    lo = *(uint32_t*)&l;
}
__device__ __forceinline__ void mma_f16(float* d, const uint32_t* a, const uint32_t* b) {
    asm volatile("mma.sync.aligned.m16n8k16.row.col.f32.f16.f16.f32 "
        "{%0,%1,%2,%3}, {%4,%5,%6,%7}, {%8,%9}, {%0,%1,%2,%3};"
        : "+f"(d[0]), "+f"(d[1]), "+f"(d[2]), "+f"(d[3])
        : "r"(a[0]), "r"(a[1]), "r"(a[2]), "r"(a[3]), "r"(b[0]), "r"(b[1]));
}

// ---------------- weight pre-conversion (f16 hi/lo) ----------------
__global__ void conv_w_kernel(const float* __restrict__ qw, const float* __restrict__ kvw,
                              const float* __restrict__ pw, const float* __restrict__ qb) {
    int idx = blockIdx.x * 256 + threadIdx.x;
    int row = idx >> 7, p = idx & 127;
    const float* src;
    uint32_t *dh, *dl;
    float sc = 1.f;
    if (row < 256)      { src = qw + row * 256;          dh = g_qwhi + row * 128 + p;          dl = g_qwlo + row * 128 + p;          sc = QSCALE; }
    else if (row < 768) { int r = row - 256; src = kvw + r * 256; dh = g_kvwhi + r * 128 + p;  dl = g_kvwlo + r * 128 + p; }
    else                { int r = row - 768; src = pw + r * 256;  dh = g_pwhi + r * 128 + p;   dl = g_pwlo + r * 128 + p; }
    uint32_t hi, lo;
    packh2_split(src[2 * p] * sc, src[2 * p + 1] * sc, hi, lo);
    *dh = hi; *dl = lo;
    if (idx < 256) g_qbs[idx] = qb[idx] * QSCALE;
}

// ---------------- pos-bias MLP ----------------
__device__ __forceinline__ void ln16(float* x, const float* g, const float* b) {
    float m = 0.f;
#pragma unroll
    for (int i = 0; i < PD; i++) m += x[i];
    m *= (1.0f / PD);
    float v = 0.f;
#pragma unroll
    for (int i = 0; i < PD; i++) { float d = x[i] - m; v += d * d; }
    v *= (1.0f / PD);
    float inv = rsqrtf(v + 1e-5f);
#pragma unroll
    for (int i = 0; i < PD; i++) x[i] = (x[i] - m) * inv * g[i] + b[i];
}

__global__ void pos_mlp_kernel(const float* __restrict__ pp_w, const float* __restrict__ pp_b,
                               const float* __restrict__ ln1_g, const float* __restrict__ ln1_b,
                               const float* __restrict__ l1_w,  const float* __restrict__ l1_b,
                               const float* __restrict__ ln2_g, const float* __restrict__ ln2_b,
                               const float* __restrict__ l2_w,  const float* __restrict__ l2_b,
                               const float* __restrict__ ln3_g, const float* __restrict__ ln3_b,
                               const float* __restrict__ l3_w,  const float* __restrict__ l3_b) {
    int p = blockIdx.x * blockDim.x + threadIdx.x;
    if (p >= LREL) return;
    float b0 = (float)(p / 31 - 15);
    float b1 = (float)(p % 31 - 15);
    float x[PD], y[PD];
#pragma unroll
    for (int o = 0; o < PD; o++) x[o] = b0 * pp_w[o * 2 + 0] + b1 * pp_w[o * 2 + 1] + pp_b[o];
    ln16(x, ln1_g, ln1_b);
#pragma unroll
    for (int o = 0; o < PD; o++) {
        float s = l1_b[o];
#pragma unroll
        for (int i = 0; i < PD; i++) s += fmaxf(x[i], 0.f) * l1_w[o * PD + i];
        y[o] = s;
    }
#pragma unroll
    for (int o = 0; o < PD; o++) x[o] = y[o];
    ln16(x, ln2_g, ln2_b);
#pragma unroll
    for (int o = 0; o < PD; o++) {
        float s = l2_b[o];
#pragma unroll
        for (int i = 0; i < PD; i++) s += fmaxf(x[i], 0.f) * l2_w[o * PD + i];
        y[o] = s;
    }
#pragma unroll
    for (int o = 0; o < PD; o++) x[o] = y[o];
    ln16(x, ln3_g, ln3_b);
#pragma unroll
    for (int h = 0; h < NHEAD; h++) {
        float s = l3_b[h];
#pragma unroll
        for (int i = 0; i < PD; i++) s += fmaxf(x[i], 0.f) * l3_w[h * PD + i];
        g_pos[p * NHEAD + h] = s;
    }
}

__global__ void rpb_fill_kernel() {
    int i = blockIdx.x * 256 + threadIdx.x;
    int h = i >> 16;
    int rem = i & 65535;
    int n = rem >> 8;
    int m = rem & 255;
    int di = (n >> 4) - (m >> 4) + 15;
    int dj = (n & 15) - (m & 15) + 15;
    g_rpb[i] = g_pos[(di * 31 + dj) * NHEAD + h];
}

// ---------------- GEMM infrastructure ----------------
// stage layout (u32): A single f16 [0,2048), Bhi [2048,4096), Blo [4096,6144)
#define SWZ(r, c) (((r) << 4) + ((c) ^ ((((r) >> 1) & 3) << 2)))
#define GS_TILE 2048
#define GS_STAGE 6144

__device__ __forceinline__ void fill_one(uint32_t sbase, int st, int baseoff, int tid,
                                         const uint32_t* src, int r0, int kc) {
#pragma unroll
    for (int i = 0; i < 2; i++) {
        int idx = tid * 2 + i;
        int row = idx >> 2, c4 = (idx & 3) << 2;
        uint32_t off = (uint32_t)((st * GS_STAGE + baseoff + SWZ(row, c4)) * 4);
        cp16(sbase + off, src + (size_t)(r0 + row) * 128 + kc * 16 + c4);
    }
}

// f16 2-term compute: D += A*(Bhi+Blo); 64 MMAs/chunk
__device__ __forceinline__ void gemm_compute(uint32_t* st, int wm, int wn, int g, int tg,
                                             float acc[4][4][4]) {
    uint32_t* sA   = st;
    uint32_t* sBhi = st + GS_TILE;
    uint32_t* sBlo = st + 2 * GS_TILE;
#pragma unroll
    for (int ks = 0; ks < 2; ks++) {
        int pc = ks * 8 + tg;
        uint32_t a[4][4], bh[4][2], bl[4][2];
#pragma unroll
        for (int mt = 0; mt < 4; mt++) {
            int ra = wm + mt * 16 + g;
            a[mt][0] = sA[SWZ(ra, pc)];
            a[mt][1] = sA[SWZ(ra + 8, pc)];
            a[mt][2] = sA[SWZ(ra, pc + 4)];
            a[mt][3] = sA[SWZ(ra + 8, pc + 4)];
        }
#pragma unroll
        for (int nt = 0; nt < 4; nt++) {
            int rb = wn + nt * 8 + g;
            bh[nt][0] = sBhi[SWZ(rb, pc)]; bh[nt][1] = sBhi[SWZ(rb, pc + 4)];
            bl[nt][0] = sBlo[SWZ(rb, pc)]; bl[nt][1] = sBlo[SWZ(rb, pc + 4)];
        }
#pragma unroll
        for (int mt = 0; mt < 4; mt++)
#pragma unroll
            for (int nt = 0; nt < 4; nt++) {
                mma_f16(acc[mt][nt], a[mt], bh[nt]);
                mma_f16(acc[mt][nt], a[mt], bl[nt]);
            }
    }
}

// ---------------- merged Q + KV projection GEMM ----------------
__global__ __launch_bounds__(256, 2)
void gemm_qkv(const float* __restrict__ q, const float* __restrict__ kfeat,
              const float* __restrict__ kv_b) {
    extern __shared__ uint32_t gsm[];
    uint32_t sbase = smem_u32(gsm);
    int tid = threadIdx.x, lane = tid & 31, wid = tid >> 5;
    int bx = blockIdx.x, m0 = blockIdx.y * 128;
    const float* A; const uint32_t *Whi, *Wlo; float* C; const float* bias; int Ncols, n0;
    if (bx < 2) { A = q;     Whi = g_qwhi;  Wlo = g_qwlo;  C = g_qh; bias = g_qbs; Ncols = 256; n0 = bx * 128; }
    else        { A = kfeat; Whi = g_kvwhi; Wlo = g_kvwlo; C = g_kv; bias = kv_b;  Ncols = 512; n0 = (bx - 2) * 128; }

    int wm = (wid >> 2) * 64, wn = (wid & 3) * 32;
    int g = lane >> 2, tg = lane & 3;
    int lrow = tid >> 3, lc4 = (tid & 7) * 4, lp = lc4 >> 1;

    float acc[4][4][4];
#pragma unroll
    for (int a = 0; a < 4; a++)
#pragma unroll
        for (int bq = 0; bq < 4; bq++)
#pragma unroll
            for (int c = 0; c < 4; c++) acc[a][bq][c] = 0.f;

    {   // prologue: pack A chunk0 (f16 single), async-fill B
        uint32_t* st0 = gsm;
#pragma unroll
        for (int it = 0; it < 4; it++) {
            int row = it * 32 + lrow;
            float4 a4 = *(const float4*)(A + (size_t)(m0 + row) * 256 + lc4);
            int p0 = SWZ(row, lp);
            st0[p0] = packh2(a4.x, a4.y);
            st0[p0 + 1] = packh2(a4.z, a4.w);
        }
        fill_one(sbase, 0, GS_TILE, tid, Whi, n0, 0);
        fill_one(sbase, 0, 2 * GS_TILE, tid, Wlo, n0, 0);
        cp_commit();
    }

    for (int kc = 0; kc < 8; kc++) {
        int s = kc & 1;
        bool pre = (kc + 1 < 8);
        float4 a4[4];
        if (pre) {
#pragma unroll
            for (int it = 0; it < 4; it++) {
                int row = it * 32 + lrow;
                a4[it] = *(const float4*)(A + (size_t)(m0 + row) * 256 + (kc + 1) * 32 + lc4);
            }
            fill_one(sbase, s ^ 1, GS_TILE, tid, Whi, n0, kc + 1);
            fill_one(sbase, s ^ 1, 2 * GS_TILE, tid, Wlo, n0, kc + 1);
            cp_commit();
            cp_wait1();
        } else {
            cp_wait0();
        }
        __syncthreads();
        gemm_compute(gsm + s * GS_STAGE, wm, wn, g, tg, acc);
        if (pre) {
            uint32_t* stn = gsm + (s ^ 1) * GS_STAGE;
#pragma unroll
            for (int it = 0; it < 4; it++) {
                int row = it * 32 + lrow;
                int p0 = SWZ(row, lp);
                stn[p0] = packh2(a4[it].x, a4[it].y);
                stn[p0 + 1] = packh2(a4[it].z, a4[it].w);
            }
        }
        __syncthreads();
    }

#pragma unroll
    for (int mt = 0; mt < 4; mt++) {
        int r0 = m0 + wm + mt * 16 + g;
#pragma unroll
        for (int nt = 0; nt < 4; nt++) {
            int col = n0 + wn + nt * 8 + 2 * tg;
            float bb0 = bias[col], bb1 = bias[col + 1];
            float2 v0, v1;
            v0.x = acc[mt][nt][0] + bb0; v0.y = acc[mt][nt][1] + bb1;
            v1.x = acc[mt][nt][2] + bb0; v1.y = acc[mt][nt][3] + bb1;
            *(float2*)(C + (size_t)r0 * Ncols + col) = v0;
            *(float2*)(C + (size_t)(r0 + 8) * Ncols + col) = v1;
        }
    }
}

// ---------------- output projection GEMM (A = f16 x, fully async) ----------------
__global__ __launch_bounds__(256, 2)
void gemm_proj(const float* __restrict__ proj_b, float* __restrict__ out) {
    extern __shared__ uint32_t gsm[];
    uint32_t sbase = smem_u32(gsm);
    int tid = threadIdx.x, lane = tid & 31, wid = tid >> 5;
    int m0 = blockIdx.y * 128, n0 = blockIdx.x * 128;
    int wm = (wid >> 2) * 64, wn = (wid & 3) * 32;
    int g = lane >> 2, tg = lane & 3;

    float acc[4][4][4];
#pragma unroll
    for (int a = 0; a < 4; a++)
#pragma unroll
        for (int bq = 0; bq < 4; bq++)
#pragma unroll
            for (int c = 0; c < 4; c++) acc[a][bq][c] = 0.f;

    fill_one(sbase, 0, 0, tid, g_xf, m0, 0);
    fill_one(sbase, 0, GS_TILE, tid, g_pwhi, n0, 0);
    fill_one(sbase, 0, 2 * GS_TILE, tid, g_pwlo, n0, 0);
    cp_commit();

    for (int kc = 0; kc < 8; kc++) {
        int s = kc & 1;
        bool pre = (kc + 1 < 8);
        if (pre) {
            fill_one(sbase, s ^ 1, 0, tid, g_xf, m0, kc + 1);
            fill_one(sbase, s ^ 1, GS_TILE, tid, g_pwhi, n0, kc + 1);
            fill_one(sbase, s ^ 1, 2 * GS_TILE, tid, g_pwlo, n0, kc + 1);
            cp_commit();
            cp_wait1();
        } else {
            cp_wait0();
        }
        __syncthreads();
        gemm_compute(gsm + s * GS_STAGE, wm, wn, g, tg, acc);
        __syncthreads();
    }

#pragma unroll
    for (int mt = 0; mt < 4; mt++) {
        int r0 = m0 + wm + mt * 16 + g;
#pragma unroll
        for (int nt = 0; nt < 4; nt++) {
            int col = n0 + wn + nt * 8 + 2 * tg;
            float bb0 = proj_b[col], bb1 = proj_b[col + 1];
            float2 v0, v1;
            v0.x = acc[mt][nt][0] + bb0; v0.y = acc[mt][nt][1] + bb1;
            v1.x = acc[mt][nt][2] + bb0; v1.y = acc[mt][nt][3] + bb1;
            *(float2*)(out + (size_t)r0 * 256 + col) = v0;
            *(float2*)(out + (size_t)(r0 + 8) * 256 + col) = v1;
        }
    }
}

// ---------------- fused attention (f16 2-term QK, f16 PV) ----------------
// K: f16 hi/lo pairs [key][16] stride 20. Q: single f16 pairs, 128 rows.
// V: f16 transposed Vt[dim][key] stride 133 u32 (round-9 layout).
#define KSTR 20
#define VSTR 133
#define A_KHI 0
#define A_KLO 5120
#define A_Q   10240
#define A_VT  12800
#define A_TOT 17056
__global__ __launch_bounds__(256, 1)
void attn_kernel(const float* __restrict__ mask) {
    extern __shared__ uint32_t smu[];
    uint32_t* Khi = smu + A_KHI;
    uint32_t* Klo = smu + A_KLO;
    uint32_t* Qs  = smu + A_Q;
    uint32_t* Vt  = smu + A_VT;
    __half*  Vth = (__half*)Vt;

    int tid = threadIdx.x, lane = tid & 31, w = tid >> 5;
    int r0 = blockIdx.x * 128, h = blockIdx.y, b = blockIdx.z;
    int g = lane >> 2, tg = lane & 3;

    {
        int key8 = tid >> 3, d4 = (tid & 7) * 4;
#pragma unroll
        for (int it = 0; it < 8; it++) {
            int key = it * 32 + key8;
            const float* src = g_kv + (size_t)(b * NTOK + key) * (2 * DIMC) + h * HD + d4;
            float4 kx = *(const float4*)src;
            float4 vx = *(const float4*)(src + DIMC);
            uint32_t h0, l0, h1, l1;
            packh2_split(kx.x, kx.y, h0, l0);
            packh2_split(kx.z, kx.w, h1, l1);
            int kb = key * KSTR + (d4 >> 1);
            Khi[kb] = h0; Khi[kb + 1] = h1;
            Klo[kb] = l0; Klo[kb + 1] = l1;
            Vth[(d4 + 0) * (2 * VSTR) + key] = __float2half_rn(vx.x);
            Vth[(d4 + 1) * (2 * VSTR) + key] = __float2half_rn(vx.y);
            Vth[(d4 + 2) * (2 * VSTR) + key] = __float2half_rn(vx.z);
            Vth[(d4 + 3) * (2 * VSTR) + key] = __float2half_rn(vx.w);
        }
#pragma unroll
        for (int it = 0; it < 4; it++) {
            int row = it * 32 + key8;
            float4 qx = *(const float4*)(g_qh + (size_t)(b * NTOK + r0 + row) * DIMC + h * HD + d4);
            int qb = row * KSTR + (d4 >> 1);
            Qs[qb] = packh2(qx.x, qx.y);
            Qs[qb + 1] = packh2(qx.z, qx.w);
        }
    }
    __syncthreads();

    int wm = w * 16;

    uint32_t q_[2][4];
#pragma unroll
    for (int ks = 0; ks < 2; ks++) {
        int ra = (wm + g) * KSTR + ks * 8 + tg;
        int rb = (wm + 8 + g) * KSTR + ks * 8 + tg;
        q_[ks][0] = Qs[ra]; q_[ks][1] = Qs[rb];
        q_[ks][2] = Qs[ra + 4]; q_[ks][3] = Qs[rb + 4];
    }

    float sc[32][4];
#pragma unroll
    for (int j = 0; j < 32; j++) { sc[j][0] = 0.f; sc[j][1] = 0.f; sc[j][2] = 0.f; sc[j][3] = 0.f; }
#pragma unroll
    for (int j = 0; j < 32; j++) {
#pragma unroll
        for (int ks = 0; ks < 2; ks++) {
            int kb = (j * 8 + g) * KSTR + ks * 8 + tg;
            uint32_t bh[2], bl[2];
            bh[0] = Khi[kb]; bh[1] = Khi[kb + 4];
            bl[0] = Klo[kb]; bl[1] = Klo[kb + 4];
            mma_f16(sc[j], q_[ks], bh);
            mma_f16(sc[j], q_[ks], bl);
        }
    }

    int R0 = r0 + wm + g;
    const float* rpbR = g_rpb + ((size_t)h * NTOK + R0) * NTOK;
    const float* mkR  = mask + ((size_t)(b & (NGROUP - 1)) * NTOK + R0) * NTOK;
#pragma unroll
    for (int j = 0; j < 32; j++) {
        int c = j * 8 + 2 * tg;
        float2 r0v = *(const float2*)(rpbR + c);
        float2 r1v = *(const float2*)(rpbR + 8 * NTOK + c);
        float2 m0v = *(const float2*)(mkR + c);
        float2 m1v = *(const float2*)(mkR + 8 * NTOK + c);
        sc[j][0] += r0v.x + m0v.x; sc[j][1] += r0v.y + m0v.y;
        sc[j][2] += r1v.x + m1v.x; sc[j][3] += r1v.y + m1v.y;
    }

    float mx0 = -1e30f, mx1 = -1e30f;
#pragma unroll
    for (int j = 0; j < 32; j++) {
        mx0 = fmaxf(mx0, fmaxf(sc[j][0], sc[j][1]));
        mx1 = fmaxf(mx1, fmaxf(sc[j][2], sc[j][3]));
    }
    mx0 = fmaxf(mx0, __shfl_xor_sync(0xffffffffu, mx0, 1));
    mx0 = fmaxf(mx0, __shfl_xor_sync(0xffffffffu, mx0, 2));
    mx1 = fmaxf(mx1, __shfl_xor_sync(0xffffffffu, mx1, 1));
    mx1 = fmaxf(mx1, __shfl_xor_sync(0xffffffffu, mx1, 2));

    uint32_t pf[16][4];
    float sum0 = 0.f, sum1 = 0.f;
#pragma unroll
    for (int jj = 0; jj < 16; jj++) {
        __half2 e0 = h2exp(__floats2half2_rn(sc[2 * jj][0] - mx0, sc[2 * jj][1] - mx0));
        __half2 e1 = h2exp(__floats2half2_rn(sc[2 * jj][2] - mx1, sc[2 * jj][3] - mx1));
        __half2 e2 = h2exp(__floats2half2_rn(sc[2 * jj + 1][0] - mx0, sc[2 * jj + 1][1] - mx0));
        __half2 e3 = h2exp(__floats2half2_rn(sc[2 * jj + 1][2] - mx1, sc[2 * jj + 1][3] - mx1));
        pf[jj][0] = *(uint32_t*)&e0;
        pf[jj][1] = *(uint32_t*)&e1;
        pf[jj][2] = *(uint32_t*)&e2;
        pf[jj][3] = *(uint32_t*)&e3;
        float2 f0 = __half22float2(e0), f1 = __half22float2(e1);
        float2 f2 = __half22float2(e2), f3 = __half22float2(e3);
        sum0 += f0.x + f0.y + f2.x + f2.y;
        sum1 += f1.x + f1.y + f3.x + f3.y;
    }
    sum0 += __shfl_xor_sync(0xffffffffu, sum0, 1);
    sum0 += __shfl_xor_sync(0xffffffffu, sum0, 2);
    sum1 += __shfl_xor_sync(0xffffffffu, sum1, 1);
    sum1 += __shfl_xor_sync(0xffffffffu, sum1, 2);
    float inv0 = 1.0f / sum0, inv1 = 1.0f / sum1;

    size_t ro0 = (size_t)(b * NTOK + R0) * 128;
    size_t ro1 = ro0 + 8 * 128;
#pragma unroll
    for (int dt = 0; dt < 4; dt++) {
        float ob[4] = {0.f, 0.f, 0.f, 0.f};
#pragma unroll
        for (int kt = 0; kt < 16; kt++) {
            int vb = (dt * 8 + g) * VSTR + kt * 8 + tg;
            uint32_t bv[2];
            bv[0] = Vt[vb]; bv[1] = Vt[vb + 4];
            mma_f16(ob, pf[kt], bv);
        }
        int pc = h * 16 + dt * 4 + tg;
        g_xf[ro0 + pc] = packh2(ob[0] * inv0, ob[1] * inv0);
        g_xf[ro1 + pc] = packh2(ob[2] * inv1, ob[3] * inv1);
    }
}

// ---------------- launch ----------------
extern "C" void kernel_launch(void* const* d_in, const int* in_sizes, int n_in,
                              void* d_out, int out_size) {
    const float* q      = (const float*)d_in[0];
    const float* k      = (const float*)d_in[1];
    const float* mask   = (const float*)d_in[2];
    const float* q_w    = (const float*)d_in[3];
    const float* q_b    = (const float*)d_in[4];
    const float* kv_w   = (const float*)d_in[5];
    const float* kv_b   = (const float*)d_in[6];
    const float* proj_w = (const float*)d_in[7];
    const float* proj_b = (const float*)d_in[8];
    const float* pp_w   = (const float*)d_in[9];
    const float* pp_b   = (const float*)d_in[10];
    const float* ln1_g  = (const float*)d_in[11];
    const float* ln1_b  = (const float*)d_in[12];
    const float* l1_w   = (const float*)d_in[13];
    const float* l1_b   = (const float*)d_in[14];
    const float* ln2_g  = (const float*)d_in[15];
    const float* ln2_b  = (const float*)d_in[16];
    const float* l2_w   = (const float*)d_in[17];
    const float* l2_b   = (const float*)d_in[18];
    const float* ln3_g  = (const float*)d_in[19];
    const float* ln3_b  = (const float*)d_in[20];
    const float* l3_w   = (const float*)d_in[21];
    const float* l3_b   = (const float*)d_in[22];
    (void)in_sizes; (void)n_in; (void)out_size;

    int gsmem = 2 * GS_STAGE * (int)sizeof(uint32_t);   // 49152
    int asmem = A_TOT * (int)sizeof(uint32_t);          // 68224
    static int attr_done = 0;
    if (!attr_done) {
        cudaFuncSetAttribute(gemm_qkv, cudaFuncAttributeMaxDynamicSharedMemorySize, gsmem);
        cudaFuncSetAttribute(gemm_proj, cudaFuncAttributeMaxDynamicSharedMemorySize, gsmem);
        cudaFuncSetAttribute(attn_kernel, cudaFuncAttributeMaxDynamicSharedMemorySize, asmem);
        attr_done = 1;
    }

    conv_w_kernel<<<512, 256>>>(q_w, kv_w, proj_w, q_b);
    pos_mlp_kernel<<<4, 256>>>(pp_w, pp_b, ln1_g, ln1_b, l1_w, l1_b,
                               ln2_g, ln2_b, l2_w, l2_b, ln3_g, ln3_b, l3_w, l3_b);
    rpb_fill_kernel<<<NHEAD * NTOK * NTOK / 256, 256>>>();

    gemm_qkv<<<dim3(6, 512), 256, gsmem>>>(q, k, kv_b);
    attn_kernel<<<dim3(2, NHEAD, BATCH), 256, asmem>>>(mask);
    gemm_proj<<<dim3(2, 512), 256, gsmem>>>(proj_b, (float*)d_out);
}

// round 17
// speedup vs baseline: 1.3693x; 1.0552x over previous
#include <cuda_runtime.h>
#include <cuda_bf16.h>
#include <cuda_fp16.h>
#include <cstdint>
#include <cstddef>

// ---------------- problem constants ----------------
#define NHEAD 8
#define HD 32
#define NTOK 256
#define BATCH 256
#define DIMC 256
#define NGROUP 64
#define PD 16
#define LREL 961
#define QSCALE 0.17677669529663687f
#define MROWS (BATCH * NTOK)

// ---------------- device scratch ----------------
__device__ float g_qh[(size_t)MROWS * DIMC];
__device__ float g_kv[(size_t)MROWS * 2 * DIMC];
__device__ float g_pos[LREL * NHEAD];
__device__ float g_rpb[NHEAD * NTOK * NTOK];
__device__ uint32_t g_qwhi[256 * 128],  g_qwlo[256 * 128];
__device__ uint32_t g_kvwhi[512 * 128], g_kvwlo[512 * 128];
__device__ uint32_t g_pw[256 * 128];            // proj weight single f16
__device__ float g_qbs[256];
__device__ uint32_t g_xf[(size_t)MROWS * 128];  // attention out, f16 pairs

// ---------------- helpers ----------------
__device__ __forceinline__ uint32_t smem_u32(const void* p) {
    uint32_t a;
    asm("{ .reg .u64 t; cvta.to.shared.u64 t, %1; cvt.u32.u64 %0, t; }" : "=r"(a) : "l"(p));
    return a;
}
__device__ __forceinline__ void cp16(uint32_t saddr, const void* g) {
    asm volatile("cp.async.cg.shared.global [%0], [%1], 16;" :: "r"(saddr), "l"(g) : "memory");
}
__device__ __forceinline__ void cp_commit() { asm volatile("cp.async.commit_group;" ::: "memory"); }
__device__ __forceinline__ void cp_wait0() { asm volatile("cp.async.wait_group 0;" ::: "memory"); }
__device__ __forceinline__ void cp_wait1() { asm volatile("cp.async.wait_group 1;" ::: "memory"); }

__device__ __forceinline__ uint32_t packh2(float x, float y) {
    __half2 h = __floats2half2_rn(x, y);
    return *(uint32_t*)&h;
}
__device__ __forceinline__ void packh2_split(float x, float y, uint32_t& hi, uint32_t& lo) {
    __half2 h = __floats2half2_rn(x, y);
    float2 f = __half22float2(h);
    __half2 l = __floats2half2_rn(x - f.x, y - f.y);
    hi = *(uint32_t*)&h;
    lo = *(uint32_t*)&l;
}
__device__ __forceinline__ void mma_f16(float* d, const uint32_t* a, const uint32_t* b) {
    asm volatile("mma.sync.aligned.m16n8k16.row.col.f32.f16.f16.f32 "
        "{%0,%1,%2,%3}, {%4,%5,%6,%7}, {%8,%9}, {%0,%1,%2,%3};"
        : "+f"(d[0]), "+f"(d[1]), "+f"(d[2]), "+f"(d[3])
        : "r"(a[0]), "r"(a[1]), "r"(a[2]), "r"(a[3]), "r"(b[0]), "r"(b[1]));
}

// ---------------- weight pre-conversion ----------------
__global__ void conv_w_kernel(const float* __restrict__ qw, const float* __restrict__ kvw,
                              const float* __restrict__ pw, const float* __restrict__ qb) {
    int idx = blockIdx.x * 256 + threadIdx.x;
    int row = idx >> 7, p = idx & 127;
    if (row < 256) {
        const float* src = qw + row * 256;
        uint32_t hi, lo;
        packh2_split(src[2 * p] * QSCALE, src[2 * p + 1] * QSCALE, hi, lo);
        g_qwhi[row * 128 + p] = hi; g_qwlo[row * 128 + p] = lo;
    } else if (row < 768) {
        int r = row - 256;
        const float* src = kvw + r * 256;
        uint32_t hi, lo;
        packh2_split(src[2 * p], src[2 * p + 1], hi, lo);
        g_kvwhi[r * 128 + p] = hi; g_kvwlo[r * 128 + p] = lo;
    } else {
        int r = row - 768;
        const float* src = pw + r * 256;
        g_pw[r * 128 + p] = packh2(src[2 * p], src[2 * p + 1]);
    }
    if (idx < 256) g_qbs[idx] = qb[idx] * QSCALE;
}

// ---------------- pos-bias MLP ----------------
__device__ __forceinline__ void ln16(float* x, const float* g, const float* b) {
    float m = 0.f;
#pragma unroll
    for (int i = 0; i < PD; i++) m += x[i];
    m *= (1.0f / PD);
    float v = 0.f;
#pragma unroll
    for (int i = 0; i < PD; i++) { float d = x[i] - m; v += d * d; }
    v *= (1.0f / PD);
    float inv = rsqrtf(v + 1e-5f);
#pragma unroll
    for (int i = 0; i < PD; i++) x[i] = (x[i] - m) * inv * g[i] + b[i];
}

__global__ void pos_mlp_kernel(const float* __restrict__ pp_w, const float* __restrict__ pp_b,
                               const float* __restrict__ ln1_g, const float* __restrict__ ln1_b,
                               const float* __restrict__ l1_w,  const float* __restrict__ l1_b,
                               const float* __restrict__ ln2_g, const float* __restrict__ ln2_b,
                               const float* __restrict__ l2_w,  const float* __restrict__ l2_b,
                               const float* __restrict__ ln3_g, const float* __restrict__ ln3_b,
                               const float* __restrict__ l3_w,  const float* __restrict__ l3_b) {
    int p = blockIdx.x * blockDim.x + threadIdx.x;
    if (p >= LREL) return;
    float b0 = (float)(p / 31 - 15);
    float b1 = (float)(p % 31 - 15);
    float x[PD], y[PD];
#pragma unroll
    for (int o = 0; o < PD; o++) x[o] = b0 * pp_w[o * 2 + 0] + b1 * pp_w[o * 2 + 1] + pp_b[o];
    ln16(x, ln1_g, ln1_b);
#pragma unroll
    for (int o = 0; o < PD; o++) {
        float s = l1_b[o];
#pragma unroll
        for (int i = 0; i < PD; i++) s += fmaxf(x[i], 0.f) * l1_w[o * PD + i];
        y[o] = s;
    }
#pragma unroll
    for (int o = 0; o < PD; o++) x[o] = y[o];
    ln16(x, ln2_g, ln2_b);
#pragma unroll
    for (int o = 0; o < PD; o++) {
        float s = l2_b[o];
#pragma unroll
        for (int i = 0; i < PD; i++) s += fmaxf(x[i], 0.f) * l2_w[o * PD + i];
        y[o] = s;
    }
#pragma unroll
    for (int o = 0; o < PD; o++) x[o] = y[o];
    ln16(x, ln3_g, ln3_b);
#pragma unroll
    for (int h = 0; h < NHEAD; h++) {
        float s = l3_b[h];
#pragma unroll
        for (int i = 0; i < PD; i++) s += fmaxf(x[i], 0.f) * l3_w[h * PD + i];
        g_pos[p * NHEAD + h] = s;
    }
}

__global__ void rpb_fill_kernel() {
    int i = blockIdx.x * 256 + threadIdx.x;
    int h = i >> 16;
    int rem = i & 65535;
    int n = rem >> 8;
    int m = rem & 255;
    int di = (n >> 4) - (m >> 4) + 15;
    int dj = (n & 15) - (m & 15) + 15;
    g_rpb[i] = g_pos[(di * 31 + dj) * NHEAD + h];
}

// ---------------- GEMM infrastructure ----------------
#define SWZ(r, c) (((r) << 4) + ((c) ^ ((((r) >> 1) & 3) << 2)))
#define GS_TILE 2048
#define GS_STAGE 6144

__device__ __forceinline__ void fill_one(uint32_t sbase, int st, int baseoff, int tid,
                                         const uint32_t* src, int r0, int kc) {
#pragma unroll
    for (int i = 0; i < 2; i++) {
        int idx = tid * 2 + i;
        int row = idx >> 2, c4 = (idx & 3) << 2;
        uint32_t off = (uint32_t)((st * GS_STAGE + baseoff + SWZ(row, c4)) * 4);
        cp16(sbase + off, src + (size_t)(r0 + row) * 128 + kc * 16 + c4);
    }
}

// 2-term: D += A*(Bhi+Blo)
__device__ __forceinline__ void gemm_compute2(uint32_t* st, int wm, int wn, int g, int tg,
                                              float acc[4][4][4]) {
    uint32_t* sA   = st;
    uint32_t* sBhi = st + GS_TILE;
    uint32_t* sBlo = st + 2 * GS_TILE;
#pragma unroll
    for (int ks = 0; ks < 2; ks++) {
        int pc = ks * 8 + tg;
        uint32_t a[4][4], bh[4][2], bl[4][2];
#pragma unroll
        for (int mt = 0; mt < 4; mt++) {
            int ra = wm + mt * 16 + g;
            a[mt][0] = sA[SWZ(ra, pc)];
            a[mt][1] = sA[SWZ(ra + 8, pc)];
            a[mt][2] = sA[SWZ(ra, pc + 4)];
            a[mt][3] = sA[SWZ(ra + 8, pc + 4)];
        }
#pragma unroll
        for (int nt = 0; nt < 4; nt++) {
            int rb = wn + nt * 8 + g;
            bh[nt][0] = sBhi[SWZ(rb, pc)]; bh[nt][1] = sBhi[SWZ(rb, pc + 4)];
            bl[nt][0] = sBlo[SWZ(rb, pc)]; bl[nt][1] = sBlo[SWZ(rb, pc + 4)];
        }
#pragma unroll
        for (int mt = 0; mt < 4; mt++)
#pragma unroll
            for (int nt = 0; nt < 4; nt++) {
                mma_f16(acc[mt][nt], a[mt], bh[nt]);
                mma_f16(acc[mt][nt], a[mt], bl[nt]);
            }
    }
}

// 1-term: D += A*B
__device__ __forceinline__ void gemm_compute1(uint32_t* st, int wm, int wn, int g, int tg,
                                              float acc[4][4][4]) {
    uint32_t* sA = st;
    uint32_t* sB = st + GS_TILE;
#pragma unroll
    for (int ks = 0; ks < 2; ks++) {
        int pc = ks * 8 + tg;
        uint32_t a[4][4], bb[4][2];
#pragma unroll
        for (int mt = 0; mt < 4; mt++) {
            int ra = wm + mt * 16 + g;
            a[mt][0] = sA[SWZ(ra, pc)];
            a[mt][1] = sA[SWZ(ra + 8, pc)];
            a[mt][2] = sA[SWZ(ra, pc + 4)];
            a[mt][3] = sA[SWZ(ra + 8, pc + 4)];
        }
#pragma unroll
        for (int nt = 0; nt < 4; nt++) {
            int rb = wn + nt * 8 + g;
            bb[nt][0] = sB[SWZ(rb, pc)]; bb[nt][1] = sB[SWZ(rb, pc + 4)];
        }
#pragma unroll
        for (int mt = 0; mt < 4; mt++)
#pragma unroll
            for (int nt = 0; nt < 4; nt++)
                mma_f16(acc[mt][nt], a[mt], bb[nt]);
    }
}

// ---------------- merged Q + KV projection GEMM ----------------
__global__ __launch_bounds__(256, 2)
void gemm_qkv(const float* __restrict__ q, const float* __restrict__ kfeat,
              const float* __restrict__ kv_b) {
    extern __shared__ uint32_t gsm[];
    uint32_t sbase = smem_u32(gsm);
    int tid = threadIdx.x, lane = tid & 31, wid = tid >> 5;
    int bx = blockIdx.x, m0 = blockIdx.y * 128;
    const float* A; const uint32_t *Whi, *Wlo; float* C; const float* bias; int Ncols, n0;
    if (bx < 2) { A = q;     Whi = g_qwhi;  Wlo = g_qwlo;  C = g_qh; bias = g_qbs; Ncols = 256; n0 = bx * 128; }
    else        { A = kfeat; Whi = g_kvwhi; Wlo = g_kvwlo; C = g_kv; bias = kv_b;  Ncols = 512; n0 = (bx - 2) * 128; }

    int wm = (wid >> 2) * 64, wn = (wid & 3) * 32;
    int g = lane >> 2, tg = lane & 3;
    int lrow = tid >> 3, lc4 = (tid & 7) * 4, lp = lc4 >> 1;

    float acc[4][4][4];
#pragma unroll
    for (int a = 0; a < 4; a++)
#pragma unroll
        for (int bq = 0; bq < 4; bq++)
#pragma unroll
            for (int c = 0; c < 4; c++) acc[a][bq][c] = 0.f;

    {
        uint32_t* st0 = gsm;
#pragma unroll
        for (int it = 0; it < 4; it++) {
            int row = it * 32 + lrow;
            float4 a4 = *(const float4*)(A + (size_t)(m0 + row) * 256 + lc4);
            int p0 = SWZ(row, lp);
            st0[p0] = packh2(a4.x, a4.y);
            st0[p0 + 1] = packh2(a4.z, a4.w);
        }
        fill_one(sbase, 0, GS_TILE, tid, Whi, n0, 0);
        fill_one(sbase, 0, 2 * GS_TILE, tid, Wlo, n0, 0);
        cp_commit();
    }

    for (int kc = 0; kc < 8; kc++) {
        int s = kc & 1;
        bool pre = (kc + 1 < 8);
        float4 a4[4];
        if (pre) {
#pragma unroll
            for (int it = 0; it < 4; it++) {
                int row = it * 32 + lrow;
                a4[it] = *(const float4*)(A + (size_t)(m0 + row) * 256 + (kc + 1) * 32 + lc4);
            }
            fill_one(sbase, s ^ 1, GS_TILE, tid, Whi, n0, kc + 1);
            fill_one(sbase, s ^ 1, 2 * GS_TILE, tid, Wlo, n0, kc + 1);
            cp_commit();
            cp_wait1();
        } else {
            cp_wait0();
        }
        __syncthreads();
        gemm_compute2(gsm + s * GS_STAGE, wm, wn, g, tg, acc);
        if (pre) {
            uint32_t* stn = gsm + (s ^ 1) * GS_STAGE;
#pragma unroll
            for (int it = 0; it < 4; it++) {
                int row = it * 32 + lrow;
                int p0 = SWZ(row, lp);
                stn[p0] = packh2(a4[it].x, a4[it].y);
                stn[p0 + 1] = packh2(a4[it].z, a4[it].w);
            }
        }
        __syncthreads();
    }

#pragma unroll
    for (int mt = 0; mt < 4; mt++) {
        int r0 = m0 + wm + mt * 16 + g;
#pragma unroll
        for (int nt = 0; nt < 4; nt++) {
            int col = n0 + wn + nt * 8 + 2 * tg;
            float bb0 = bias[col], bb1 = bias[col + 1];
            float2 v0, v1;
            v0.x = acc[mt][nt][0] + bb0; v0.y = acc[mt][nt][1] + bb1;
            v1.x = acc[mt][nt][2] + bb0; v1.y = acc[mt][nt][3] + bb1;
            *(float2*)(C + (size_t)r0 * Ncols + col) = v0;
            *(float2*)(C + (size_t)(r0 + 8) * Ncols + col) = v1;
        }
    }
}

// ---------------- output projection GEMM (single-f16 both sides) ----------------
__global__ __launch_bounds__(256, 2)
void gemm_proj(const float* __restrict__ proj_b, float* __restrict__ out) {
    extern __shared__ uint32_t gsm[];
    uint32_t sbase = smem_u32(gsm);
    int tid = threadIdx.x, lane = tid & 31, wid = tid >> 5;
    int m0 = blockIdx.y * 128, n0 = blockIdx.x * 128;
    int wm = (wid >> 2) * 64, wn = (wid & 3) * 32;
    int g = lane >> 2, tg = lane & 3;

    float acc[4][4][4];
#pragma unroll
    for (int a = 0; a < 4; a++)
#pragma unroll
        for (int bq = 0; bq < 4; bq++)
#pragma unroll
            for (int c = 0; c < 4; c++) acc[a][bq][c] = 0.f;

    fill_one(sbase, 0, 0, tid, g_xf, m0, 0);
    fill_one(sbase, 0, GS_TILE, tid, g_pw, n0, 0);
    cp_commit();

    for (int kc = 0; kc < 8; kc++) {
        int s = kc & 1;
        bool pre = (kc + 1 < 8);
        if (pre) {
            fill_one(sbase, s ^ 1, 0, tid, g_xf, m0, kc + 1);
            fill_one(sbase, s ^ 1, GS_TILE, tid, g_pw, n0, kc + 1);
            cp_commit();
            cp_wait1();
        } else {
            cp_wait0();
        }
        __syncthreads();
        gemm_compute1(gsm + s * GS_STAGE, wm, wn, g, tg, acc);
        __syncthreads();
    }

#pragma unroll
    for (int mt = 0; mt < 4; mt++) {
        int r0 = m0 + wm + mt * 16 + g;
#pragma unroll
        for (int nt = 0; nt < 4; nt++) {
            int col = n0 + wn + nt * 8 + 2 * tg;
            float bb0 = proj_b[col], bb1 = proj_b[col + 1];
            float2 v0, v1;
            v0.x = acc[mt][nt][0] + bb0; v0.y = acc[mt][nt][1] + bb1;
            v1.x = acc[mt][nt][2] + bb0; v1.y = acc[mt][nt][3] + bb1;
            *(float2*)(out + (size_t)r0 * 256 + col) = v0;
            *(float2*)(out + (size_t)(r0 + 8) * 256 + col) = v1;
        }
    }
}

// ---------------- fused attention (single-f16 QK, f16 PV) ----------------
// K: f16 pairs [key][16] stride 20. Q: same, 128 rows. V: f16 Vt[dim][key] stride 133.
#define KSTR 20
#define VSTR 133
#define A_K   0
#define A_Q   5120
#define A_VT  7680
#define A_TOT 11936
__global__ __launch_bounds__(256, 1)
void attn_kernel(const float* __restrict__ mask) {
    extern __shared__ uint32_t smu[];
    uint32_t* Ks = smu + A_K;
    uint32_t* Qs = smu + A_Q;
    uint32_t* Vt = smu + A_VT;
    __half*  Vth = (__half*)Vt;

    int tid = threadIdx.x, lane = tid & 31, w = tid >> 5;
    int r0 = blockIdx.x * 128, h = blockIdx.y, b = blockIdx.z;
    int g = lane >> 2, tg = lane & 3;

    {
        int key8 = tid >> 3, d4 = (tid & 7) * 4;
#pragma unroll
        for (int it = 0; it < 8; it++) {
            int key = it * 32 + key8;
            const float* src = g_kv + (size_t)(b * NTOK + key) * (2 * DIMC) + h * HD + d4;
            float4 kx = *(const float4*)src;
            float4 vx = *(const float4*)(src + DIMC);
            int kb = key * KSTR + (d4 >> 1);
            Ks[kb] = packh2(kx.x, kx.y);
            Ks[kb + 1] = packh2(kx.z, kx.w);
            Vth[(d4 + 0) * (2 * VSTR) + key] = __float2half_rn(vx.x);
            Vth[(d4 + 1) * (2 * VSTR) + key] = __float2half_rn(vx.y);
            Vth[(d4 + 2) * (2 * VSTR) + key] = __float2half_rn(vx.z);
            Vth[(d4 + 3) * (2 * VSTR) + key] = __float2half_rn(vx.w);
        }
#pragma unroll
        for (int it = 0; it < 4; it++) {
            int row = it * 32 + key8;
            float4 qx = *(const float4*)(g_qh + (size_t)(b * NTOK + r0 + row) * DIMC + h * HD + d4);
            int qb = row * KSTR + (d4 >> 1);
            Qs[qb] = packh2(qx.x, qx.y);
            Qs[qb + 1] = packh2(qx.z, qx.w);
        }
    }
    __syncthreads();

    int wm = w * 16;

    uint32_t q_[2][4];
#pragma unroll
    for (int ks = 0; ks < 2; ks++) {
        int ra = (wm + g) * KSTR + ks * 8 + tg;
        int rb = (wm + 8 + g) * KSTR + ks * 8 + tg;
        q_[ks][0] = Qs[ra]; q_[ks][1] = Qs[rb];
        q_[ks][2] = Qs[ra + 4]; q_[ks][3] = Qs[rb + 4];
    }

    float sc[32][4];
#pragma unroll
    for (int j = 0; j < 32; j++) { sc[j][0] = 0.f; sc[j][1] = 0.f; sc[j][2] = 0.f; sc[j][3] = 0.f; }
#pragma unroll
    for (int j = 0; j < 32; j++) {
#pragma unroll
        for (int ks = 0; ks < 2; ks++) {
            int kb = (j * 8 + g) * KSTR + ks * 8 + tg;
            uint32_t bh[2];
            bh[0] = Ks[kb]; bh[1] = Ks[kb + 4];
            mma_f16(sc[j], q_[ks], bh);
        }
    }

    int R0 = r0 + wm + g;
    const float* rpbR = g_rpb + ((size_t)h * NTOK + R0) * NTOK;
    const float* mkR  = mask + ((size_t)(b & (NGROUP - 1)) * NTOK + R0) * NTOK;
#pragma unroll
    for (int j = 0; j < 32; j++) {
        int c = j * 8 + 2 * tg;
        float2 r0v = *(const float2*)(rpbR + c);
        float2 r1v = *(const float2*)(rpbR + 8 * NTOK + c);
        float2 m0v = *(const float2*)(mkR + c);
        float2 m1v = *(const float2*)(mkR + 8 * NTOK + c);
        sc[j][0] += r0v.x + m0v.x; sc[j][1] += r0v.y + m0v.y;
        sc[j][2] += r1v.x + m1v.x; sc[j][3] += r1v.y + m1v.y;
    }

    float mx0 = -1e30f, mx1 = -1e30f;
#pragma unroll
    for (int j = 0; j < 32; j++) {
        mx0 = fmaxf(mx0, fmaxf(sc[j][0], sc[j][1]));
        mx1 = fmaxf(mx1, fmaxf(sc[j][2], sc[j][3]));
    }
    mx0 = fmaxf(mx0, __shfl_xor_sync(0xffffffffu, mx0, 1));
    mx0 = fmaxf(mx0, __shfl_xor_sync(0xffffffffu, mx0, 2));
    mx1 = fmaxf(mx1, __shfl_xor_sync(0xffffffffu, mx1, 1));
    mx1 = fmaxf(mx1, __shfl_xor_sync(0xffffffffu, mx1, 2));

    uint32_t pf[16][4];
    float sum0 = 0.f, sum1 = 0.f;
#pragma unroll
    for (int jj = 0; jj < 16; jj++) {
        __half2 e0 = h2exp(__floats2half2_rn(sc[2 * jj][0] - mx0, sc[2 * jj][1] - mx0));
        __half2 e1 = h2exp(__floats2half2_rn(sc[2 * jj][2] - mx1, sc[2 * jj][3] - mx1));
        __half2 e2 = h2exp(__floats2half2_rn(sc[2 * jj + 1][0] - mx0, sc[2 * jj + 1][1] - mx0));
        __half2 e3 = h2exp(__floats2half2_rn(sc[2 * jj + 1][2] - mx1, sc[2 * jj + 1][3] - mx1));
        pf[jj][0] = *(uint32_t*)&e0;
        pf[jj][1] = *(uint32_t*)&e1;
        pf[jj][2] = *(uint32_t*)&e2;
        pf[jj][3] = *(uint32_t*)&e3;
        float2 f0 = __half22float2(e0), f1 = __half22float2(e1);
        float2 f2 = __half22float2(e2), f3 = __half22float2(e3);
        sum0 += f0.x + f0.y + f2.x + f2.y;
        sum1 += f1.x + f1.y + f3.x + f3.y;
    }
    sum0 += __shfl_xor_sync(0xffffffffu, sum0, 1);
    sum0 += __shfl_xor_sync(0xffffffffu, sum0, 2);
    sum1 += __shfl_xor_sync(0xffffffffu, sum1, 1);
    sum1 += __shfl_xor_sync(0xffffffffu, sum1, 2);
    float inv0 = 1.0f / sum0, inv1 = 1.0f / sum1;

    size_t ro0 = (size_t)(b * NTOK + R0) * 128;
    size_t ro1 = ro0 + 8 * 128;
#pragma unroll
    for (int dt = 0; dt < 4; dt++) {
        float ob[4] = {0.f, 0.f, 0.f, 0.f};
#pragma unroll
        for (int kt = 0; kt < 16; kt++) {
            int vb = (dt * 8 + g) * VSTR + kt * 8 + tg;
            uint32_t bv[2];
            bv[0] = Vt[vb]; bv[1] = Vt[vb + 4];
            mma_f16(ob, pf[kt], bv);
        }
        int pc = h * 16 + dt * 4 + tg;
        g_xf[ro0 + pc] = packh2(ob[0] * inv0, ob[1] * inv0);
        g_xf[ro1 + pc] = packh2(ob[2] * inv1, ob[3] * inv1);
    }
}

// ---------------- launch ----------------
extern "C" void kernel_launch(void* const* d_in, const int* in_sizes, int n_in,
                              void* d_out, int out_size) {
    const float* q      = (const float*)d_in[0];
    const float* k      = (const float*)d_in[1];
    const float* mask   = (const float*)d_in[2];
    const float* q_w    = (const float*)d_in[3];
    const float* q_b    = (const float*)d_in[4];
    const float* kv_w   = (const float*)d_in[5];
    const float* kv_b   = (const float*)d_in[6];
    const float* proj_w = (const float*)d_in[7];
    const float* proj_b = (const float*)d_in[8];
    const float* pp_w   = (const float*)d_in[9];
    const float* pp_b   = (const float*)d_in[10];
    const float* ln1_g  = (const float*)d_in[11];
    const float* ln1_b  = (const float*)d_in[12];
    const float* l1_w   = (const float*)d_in[13];
    const float* l1_b   = (const float*)d_in[14];
    const float* ln2_g  = (const float*)d_in[15];
    const float* ln2_b  = (const float*)d_in[16];
    const float* l2_w   = (const float*)d_in[17];
    const float* l2_b   = (const float*)d_in[18];
    const float* ln3_g  = (const float*)d_in[19];
    const float* ln3_b  = (const float*)d_in[20];
    const float* l3_w   = (const float*)d_in[21];
    const float* l3_b   = (const float*)d_in[22];
    (void)in_sizes; (void)n_in; (void)out_size;

    int gsmem = 2 * GS_STAGE * (int)sizeof(uint32_t);   // 49152
    int asmem = A_TOT * (int)sizeof(uint32_t);          // 47744
    static int attr_done = 0;
    if (!attr_done) {
        cudaFuncSetAttribute(gemm_qkv, cudaFuncAttributeMaxDynamicSharedMemorySize, gsmem);
        cudaFuncSetAttribute(gemm_proj, cudaFuncAttributeMaxDynamicSharedMemorySize, gsmem);
        cudaFuncSetAttribute(attn_kernel, cudaFuncAttributeMaxDynamicSharedMemorySize, asmem);
        attr_done = 1;
    }

    conv_w_kernel<<<512, 256>>>(q_w, kv_w, proj_w, q_b);
    pos_mlp_kernel<<<4, 256>>>(pp_w, pp_b, ln1_g, ln1_b, l1_w, l1_b,
                               ln2_g, ln2_b, l2_w, l2_b, ln3_g, ln3_b, l3_w, l3_b);
    rpb_fill_kernel<<<NHEAD * NTOK * NTOK / 256, 256>>>();

    gemm_qkv<<<dim3(6, 512), 256, gsmem>>>(q, k, kv_b);
    attn_kernel<<<dim3(2, NHEAD, BATCH), 256, asmem>>>(mask);
    gemm_proj<<<dim3(2, 512), 256, gsmem>>>(proj_b, (float*)d_out);
}